// round 16
// baseline (speedup 1.0000x reference)
#include <cuda_runtime.h>
#include <stdint.h>

#define NN 21824
#define BBATCH 16
#define NCLS 80
#define CONF_T 0.05f
#define IOU_T 0.5f

typedef unsigned short u16;
typedef unsigned int u32;
typedef unsigned long long u64;

// key16 range for scores in (CONF, 2): [0x3D4C, 0x4000) -> bins (key>>1)-7846 in [0,346)
#define BIN_BASE 7846
#define HBINS 512
#define SAMPLE_RANK 30u

// k_final binary-search bounds
#define BS_LO 7846
#define BS_HI 8192

// Scratch (static device globals; no runtime allocation)
__device__ __align__(16) u16 g_keys[(size_t)BBATCH * NCLS * NN];  // 16-bit score keys [b][c][n]
__device__ float g_cls_s[BBATCH * NCLS * 100];          // per-class top-100 scores
__device__ float g_cls_b[BBATCH * NCLS * 100 * 4];      // per-class top-100 boxes

// ---------------------------------------------------------------------------
// Kernel 1: fused score compute + transpose -> 16-bit keys. 64-anchor tiles.
// ---------------------------------------------------------------------------
__global__ __launch_bounds__(256) void k_transpose(const float* __restrict__ clfs,
                                                   const float* __restrict__ ctrs) {
  int b = blockIdx.y;
  int n0 = blockIdx.x * 64;          // NN = 341*64 exactly
  __shared__ float tile[80][66];
  __shared__ float ctr[64];
  int tid = threadIdx.x;
  if (tid < 64) ctr[tid] = ctrs[b * NN + n0 + tid];
  const float4* src = (const float4*)(clfs + ((size_t)b * NN + n0) * NCLS);
  for (int k4 = tid; k4 < 1280; k4 += 256) {   // 64*80/4
    float4 v = src[k4];
    int x = k4 / 20, c = (k4 % 20) * 4;        // e = 4*k4; c = e%80 (no wrap), x = e/80
    tile[c][x] = v.x;
    tile[c + 1][x] = v.y;
    tile[c + 2][x] = v.z;
    tile[c + 3][x] = v.w;
  }
  __syncthreads();
  for (int k = tid; k < 2560; k += 256) {
    int c = k >> 5, xi = (k & 31) * 2;
    float s0 = __fmul_rn(tile[c][xi], ctr[xi]);
    float s1 = __fmul_rn(tile[c][xi + 1], ctr[xi + 1]);
    u32 k0 = s0 > CONF_T ? (__float_as_uint(s0) >> 16) : 0u;
    u32 k1 = s1 > CONF_T ? (__float_as_uint(s1) >> 16) : 0u;
    u32* dst = (u32*)(g_keys + ((size_t)b * NCLS + c) * NN + n0);
    dst[k & 31] = k0 | (k1 << 16);
  }
}

// ---------------------------------------------------------------------------
// Kernel 2: per-(b,c) top-256 selection via sampled threshold (+exact
// fallback) + greedy NMS, 512 threads/block.
// ---------------------------------------------------------------------------
__global__ __launch_bounds__(512, 2) void k_select(const float* __restrict__ regs,
                                                   const float* __restrict__ clfs,
                                                   const float* __restrict__ ctrs) {
  const int c = blockIdx.x, b = blockIdx.y;
  const int tid = threadIdx.x;
  const int lane = tid & 31, wid = tid >> 5;

  __shared__ __align__(16) u64 buf[2048];    // sort buffer (16 KB)
  __shared__ __align__(16) u32 mask[256][8]; // suppression bitmask (8 KB)
  __shared__ u32 hist[HBINS];
  __shared__ float4 bbx[256];
  __shared__ float bar[256];
  __shared__ u32 chs[257];
  __shared__ u32 validw[8], keepw[8];
  __shared__ int s_tb, s_V, s_cnt;
  __shared__ int warpcnt[8];

  float* ocs = g_cls_s + ((size_t)b * NCLS + c) * 100;
  float* ocb = g_cls_b + ((size_t)b * NCLS + c) * 400;

  const u16* colkeys = g_keys + (size_t)(b * NCLS + c) * NN;
  const uint4* gk4 = (const uint4*)colkeys;
  const u32* gk2 = (const u32*)colkeys;

  // ---- Phase A: histogram of 1024 SAMPLED keys only ----
  hist[tid] = 0u;
  if (tid == 0) { s_tb = 0; s_V = 0; s_cnt = 0; }
  __syncthreads();
#pragma unroll
  for (int s = tid; s < 1024; s += 512) {
    u32 h = colkeys[s * 21];            // max index 21483 < NN
    if (h) atomicAdd(&hist[(h >> 1) - BIN_BASE], 1u);
  }
  __syncthreads();

  // Suffix scan: largest bin tb with sample-count(bin >= tb) >= SAMPLE_RANK
  u32 h0 = 0, h1 = 0;
  if (tid < 256) {
    h0 = hist[2 * tid]; h1 = hist[2 * tid + 1];
    chs[tid] = h0 + h1;
  }
  __syncthreads();
  if (tid == 0) {
    u32 run = 0;
    for (int i = 255; i >= 0; i--) { u32 t = chs[i]; chs[i] = run; run += t; }
    chs[256] = run;
  }
  __syncthreads();
  if (tid < 256) {
    u32 running = chs[tid];
    if (running + h1 >= SAMPLE_RANK && running < SAMPLE_RANK) s_tb = 2 * tid + 1;
    u32 r2 = running + h1;
    if (r2 + h0 >= SAMPLE_RANK && r2 < SAMPLE_RANK) s_tb = 2 * tid;
  }
  __syncthreads();
  u32 T2 = (u32)(2 * (s_tb + BIN_BASE));   // conservative: collects >= ~650 keys whp

  // ---- Collect candidates >= T2; count ALL nonzero keys ----
  const float* clfb = clfs + (size_t)b * NN * NCLS + c;
  const float* ctrb = ctrs + (size_t)b * NN;
  {
    int cl = 0;
    for (int j = tid; j < NN / 2; j += 512) {
      u32 w = gk2[j];
      u32 klo = w & 0xFFFFu, khi = w >> 16;
      cl += (klo != 0u) + (khi != 0u);
      if (klo >= T2) {
        int n = 2 * j;
        u32 sb = __float_as_uint(__fmul_rn(clfb[(size_t)n * NCLS], ctrb[n]));
        int p = atomicAdd(&s_V, 1);
        if (p < 2048) buf[p] = ((u64)sb << 32) | (u64)(0xFFFFFFFFu - (u32)n);
      }
      if (khi >= T2) {
        int n = 2 * j + 1;
        u32 sb = __float_as_uint(__fmul_rn(clfb[(size_t)n * NCLS], ctrb[n]));
        int p = atomicAdd(&s_V, 1);
        if (p < 2048) buf[p] = ((u64)sb << 32) | (u64)(0xFFFFFFFFu - (u32)n);
      }
    }
    for (int o = 16; o; o >>= 1) cl += __shfl_down_sync(0xFFFFFFFFu, cl, o);
    if (lane == 0 && cl) atomicAdd(&s_cnt, cl);
  }
  __syncthreads();
  {
    int Vr = s_V, total = s_cnt;
    bool ok = (Vr <= 2048) && (Vr >= 256 || Vr >= total);
    if (!ok) {
      // ---- Exact fallback: full histogram over all keys ----
      hist[tid] = 0u;
      if (tid == 0) { s_tb = 0; s_V = 0; }
      __syncthreads();
      for (int i = tid; i < NN / 8; i += 512) {
        uint4 w = gk4[i];
        u32 h;
        h = w.x & 0xFFFFu; if (h) atomicAdd(&hist[(h >> 1) - BIN_BASE], 1u);
        h = w.x >> 16;     if (h) atomicAdd(&hist[(h >> 1) - BIN_BASE], 1u);
        h = w.y & 0xFFFFu; if (h) atomicAdd(&hist[(h >> 1) - BIN_BASE], 1u);
        h = w.y >> 16;     if (h) atomicAdd(&hist[(h >> 1) - BIN_BASE], 1u);
        h = w.z & 0xFFFFu; if (h) atomicAdd(&hist[(h >> 1) - BIN_BASE], 1u);
        h = w.z >> 16;     if (h) atomicAdd(&hist[(h >> 1) - BIN_BASE], 1u);
        h = w.w & 0xFFFFu; if (h) atomicAdd(&hist[(h >> 1) - BIN_BASE], 1u);
        h = w.w >> 16;     if (h) atomicAdd(&hist[(h >> 1) - BIN_BASE], 1u);
      }
      __syncthreads();
      u32 f0 = 0, f1 = 0;
      if (tid < 256) {
        f0 = hist[2 * tid]; f1 = hist[2 * tid + 1];
        chs[tid] = f0 + f1;
      }
      __syncthreads();
      if (tid == 0) {
        u32 run = 0;
        for (int i = 255; i >= 0; i--) { u32 t = chs[i]; chs[i] = run; run += t; }
        chs[256] = run;
      }
      __syncthreads();
      if (tid < 256) {
        u32 running = chs[tid];
        if (running + f1 >= 256u && running < 256u) s_tb = 2 * tid + 1;
        u32 r2 = running + f1;
        if (r2 + f0 >= 256u && r2 < 256u) s_tb = 2 * tid;
      }
      __syncthreads();
      u32 T2f = (u32)(2 * (s_tb + BIN_BASE));
      for (int j = tid; j < NN / 2; j += 512) {
        u32 w = gk2[j];
        u32 klo = w & 0xFFFFu, khi = w >> 16;
        if (klo >= T2f) {
          int n = 2 * j;
          u32 sb = __float_as_uint(__fmul_rn(clfb[(size_t)n * NCLS], ctrb[n]));
          int p = atomicAdd(&s_V, 1);
          if (p < 2048) buf[p] = ((u64)sb << 32) | (u64)(0xFFFFFFFFu - (u32)n);
        }
        if (khi >= T2f) {
          int n = 2 * j + 1;
          u32 sb = __float_as_uint(__fmul_rn(clfb[(size_t)n * NCLS], ctrb[n]));
          int p = atomicAdd(&s_V, 1);
          if (p < 2048) buf[p] = ((u64)sb << 32) | (u64)(0xFFFFFFFFu - (u32)n);
        }
      }
      __syncthreads();
    }
  }

  int V = s_V; if (V > 2048) V = 2048;
  const int M = (V <= 1024) ? 1024 : 2048;
  for (int i = V + tid; i < M; i += 512) buf[i] = 0ull;
  __syncthreads();

  // ---- Bitonic sort descending (keys unique -> deterministic result) ----
  u64 key = 0ull;
  if (M == 1024) {
    // 2 elements/thread: positions tid (v0) and tid+512 (v1).
    u64 v0 = buf[tid], v1 = buf[tid + 512];
    for (int k = 2; k <= 1024; k <<= 1) {
      for (int j = k >> 1; j > 0; j >>= 1) {
        if (j == 512) {
          // partner within thread; k==1024: slot0 keeps max
          u64 mx = (v0 >= v1) ? v0 : v1;
          u64 mn = (v0 >= v1) ? v1 : v0;
          v0 = mx; v1 = mn;
        } else {
          u64 q0, q1;
          if (j >= 32) {
            __syncthreads();
            buf[tid] = v0; buf[tid + 512] = v1;
            __syncthreads();
            q0 = buf[tid ^ j];
            q1 = buf[(tid ^ j) + 512];
          } else {
            u32 lo0 = (u32)v0, hi0 = (u32)(v0 >> 32);
            u32 lo1 = (u32)v1, hi1 = (u32)(v1 >> 32);
            lo0 = __shfl_xor_sync(0xFFFFFFFFu, lo0, j);
            hi0 = __shfl_xor_sync(0xFFFFFFFFu, hi0, j);
            lo1 = __shfl_xor_sync(0xFFFFFFFFu, lo1, j);
            hi1 = __shfl_xor_sync(0xFFFFFFFFu, hi1, j);
            q0 = ((u64)hi0 << 32) | lo0;
            q1 = ((u64)hi1 << 32) | lo1;
          }
          bool jz = ((tid & j) == 0);
          bool km0, km1;
          if (k == 1024) { km0 = jz; km1 = jz; }
          else if (k == 512) { km0 = jz; km1 = !jz; }
          else { bool kz = ((tid & k) == 0); km0 = (jz == kz); km1 = km0; }
          u64 mx0 = (v0 >= q0) ? v0 : q0, mn0 = (v0 >= q0) ? q0 : v0;
          u64 mx1 = (v1 >= q1) ? v1 : q1, mn1 = (v1 >= q1) ? q1 : v1;
          v0 = km0 ? mx0 : mn0;
          v1 = km1 ? mx1 : mn1;
        }
      }
    }
    key = v0;                     // position tid (descending)
    __syncthreads();
  } else {
    for (int k = 2; k <= M; k <<= 1) {
      for (int j = k >> 1; j > 0; j >>= 1) {
        for (int i = tid; i < M; i += 512) {
          int l = i ^ j;
          if (l > i) {
            u64 a = buf[i], bb2 = buf[l];
            bool up = ((i & k) == 0);
            if (up ? (a < bb2) : (a > bb2)) { buf[i] = bb2; buf[l] = a; }
          }
        }
        __syncthreads();
      }
    }
    key = (tid < 256) ? buf[tid] : 0ull;
  }

  // ---- Extract 256 candidates, decode boxes (threads 0..255) ----
  float sc = 0.f;
  bool valid = false;
  if (tid < 256) {
    sc = __uint_as_float((u32)(key >> 32));
    valid = sc > CONF_T;
    float y1 = 0.f, x1 = 0.f, y2 = 0.f, x2 = 0.f;
    if (valid) {
      int n = (int)(0xFFFFFFFFu - (u32)key);
      int off, g, lvl;
      if (n < 16384)      { lvl = 0; off = 0;     g = 7; }
      else if (n < 20480) { lvl = 1; off = 16384; g = 6; }
      else if (n < 21504) { lvl = 2; off = 20480; g = 5; }
      else if (n < 21760) { lvl = 3; off = 21504; g = 4; }
      else                { lvl = 4; off = 21760; g = 3; }
      int m = n - off;
      float gx = (float)(m >> g);              // meshgrid 'xy': x is the major axis
      float gy = (float)(m & ((1 << g) - 1));
      float sv = (float)(8 << lvl);
      float4 r = ((const float4*)regs)[(size_t)b * NN + n];
      y1 = __fmul_rn(gy - r.z, sv);
      x1 = __fmul_rn(gx - r.x, sv);
      y2 = __fmul_rn(gy + r.w, sv);
      x2 = __fmul_rn(gx + r.y, sv);
    }
    bbx[tid] = make_float4(y1, x1, y2, x2);
    bar[tid] = __fmul_rn(y2 - y1, x2 - x1);
    u32 vb = __ballot_sync(0xFFFFFFFFu, valid);
    if (lane == 0) validw[wid] = vb;
  }
  ((uint4*)mask)[tid] = make_uint4(0u, 0u, 0u, 0u);   // zero all 2048 words
  __syncthreads();

  // ---- Suppression bitmask: 1152 upper-triangle words balanced over 512 thr
  // Divide-free predicate, bit-exact to RN(inter/max(uni,1e-8)) > 0.5.
  for (int tt = tid; tt < 1152; tt += 512) {
    int g;
    if (tt < 480) g = (tt < 256) ? 0 : 1;
    else if (tt < 832) g = (tt < 672) ? 2 : 3;
    else if (tt < 1056) g = (tt < 960) ? 4 : 5;
    else g = (tt < 1120) ? 6 : 7;
    int local = tt - 16 * g * (17 - g);        // base(g) = 16*g*(17-g)
    int i = g * 32 + (local & 31);
    int w = g + (local >> 5);
    const float4 ib = bbx[i];
    const float ia = bar[i];
    u32 bits = 0;
    int j = (w == g) ? (i + 1) : (w * 32);
    int j1 = w * 32 + 32;
    for (; j < j1; j++) {
      float4 jb = bbx[j];
      float ih = fminf(ib.z, jb.z) - fmaxf(ib.x, jb.x);
      float iw = fminf(ib.w, jb.w) - fmaxf(ib.y, jb.y);
      ih = fmaxf(ih, 0.f); iw = fmaxf(iw, 0.f);
      float inter = __fmul_rn(ih, iw);
      float uni = ia + bar[j] - inter;
      float halfu = __fmul_rn(0.5f, fmaxf(uni, 1e-8f));
      if (inter > halfu) bits |= (1u << (j & 31));
    }
    mask[i][w] = bits;
  }
  __syncthreads();

  // ---- Greedy scan (single thread, branchless) ----
  if (tid == 0) {
    u32 kw[8];
#pragma unroll
    for (int w = 0; w < 8; w++) kw[w] = validw[w];
    for (int i = 0; i < 256; i++) {
      const uint4* mr = (const uint4*)&mask[i][0];
      uint4 m0 = mr[0], m1 = mr[1];
      u32 bit = (kw[i >> 5] >> (i & 31)) & 1u;
      u32 sel = (u32)(-(int)bit);
      kw[0] &= ~(m0.x & sel); kw[1] &= ~(m0.y & sel);
      kw[2] &= ~(m0.z & sel); kw[3] &= ~(m0.w & sel);
      kw[4] &= ~(m1.x & sel); kw[5] &= ~(m1.y & sel);
      kw[6] &= ~(m1.z & sel); kw[7] &= ~(m1.w & sel);
    }
#pragma unroll
    for (int w = 0; w < 8; w++) keepw[w] = kw[w];
  }
  __syncthreads();

  // ---- Compact survivors (score-descending) into per-class top-100 ----
  bool kept = false;
  u32 kb = 0;
  if (tid < 256) {
    kept = (keepw[wid] >> lane) & 1u;
    kb = __ballot_sync(0xFFFFFFFFu, kept);
    if (lane == 0) warpcnt[wid] = __popc(kb);
  }
  for (int i = tid; i < 100; i += 512) ocs[i] = 0.f;
  for (int i = tid; i < 400; i += 512) ocb[i] = 0.f;
  __syncthreads();
  if (tid < 256) {
    int base = 0;
    for (int w = 0; w < wid; w++) base += warpcnt[w];
    int rank = base + __popc(kb & ((1u << lane) - 1u));
    if (kept && rank < 100) {
      ocs[rank] = sc;
      float4 bb = bbx[tid];
      ocb[rank * 4 + 0] = bb.x;
      ocb[rank * 4 + 1] = bb.y;
      ocb[rank * 4 + 2] = bb.z;
      ocb[rank * 4 + 3] = bb.w;
    }
  }
}

// ---------------------------------------------------------------------------
// Kernel 3: per-batch stable top-100 of 8000 via threshold search + small sort
// ---------------------------------------------------------------------------
__global__ __launch_bounds__(256) void k_final(float* __restrict__ out) {
  int b = blockIdx.x, tid = threadIdx.x;
  const int lane = tid & 31;
  __shared__ __align__(16) u32 skeys[4000];   // 8000 u16 keys
  __shared__ u64 fbuf[1024];
  __shared__ int s_cnt, s_V;
  const float* cs = g_cls_s + (size_t)b * 8000;

  if (tid == 0) { s_cnt = 0; s_V = 0; }
  const float2* cs2 = (const float2*)cs;
  int cl = 0;
  for (int i = tid; i < 4000; i += 256) {
    float2 v = cs2[i];
    u32 k0 = v.x > 0.f ? (__float_as_uint(v.x) >> 16) : 0u;
    u32 k1 = v.y > 0.f ? (__float_as_uint(v.y) >> 16) : 0u;
    skeys[i] = k0 | (k1 << 16);
    cl += (k0 != 0u) + (k1 != 0u);
  }
  __syncthreads();
  for (int o = 16; o; o >>= 1) cl += __shfl_down_sync(0xFFFFFFFFu, cl, o);
  if (lane == 0 && cl) atomicAdd(&s_cnt, cl);
  __syncthreads();
  const int total = s_cnt;
  const int target = total < 100 ? total : 100;

  u32 T2 = 0;
  if (target > 0) {
    const uint4* sa4 = (const uint4*)skeys;
    int lo = BS_LO, hi = BS_HI;
    while (hi - lo > 1) {
      int mid = (lo + hi) >> 1;
      u32 T = (u32)(2 * mid);
      __syncthreads();
      if (tid == 0) s_cnt = 0;
      __syncthreads();
      int cc = 0;
      for (int i = tid; i < 1000; i += 256) {
        uint4 w = sa4[i];
        cc += ((w.x & 0xFFFFu) >= T) + ((w.x >> 16) >= T)
            + ((w.y & 0xFFFFu) >= T) + ((w.y >> 16) >= T)
            + ((w.z & 0xFFFFu) >= T) + ((w.z >> 16) >= T)
            + ((w.w & 0xFFFFu) >= T) + ((w.w >> 16) >= T);
      }
      for (int o = 16; o; o >>= 1) cc += __shfl_down_sync(0xFFFFFFFFu, cc, o);
      if (lane == 0 && cc) atomicAdd(&s_cnt, cc);
      __syncthreads();
      if (s_cnt >= target) lo = mid; else hi = mid;
    }
    T2 = (u32)(2 * lo);

    for (int j = tid; j < 4000; j += 256) {
      u32 w = skeys[j];
      u32 klo = w & 0xFFFFu, khi = w >> 16;
      if (klo >= T2) {
        int n = 2 * j;
        int p = atomicAdd(&s_V, 1);
        if (p < 1024)
          fbuf[p] = ((u64)__float_as_uint(cs[n]) << 32) | (u64)(0xFFFFFFFFu - (u32)n);
      }
      if (khi >= T2) {
        int n = 2 * j + 1;
        int p = atomicAdd(&s_V, 1);
        if (p < 1024)
          fbuf[p] = ((u64)__float_as_uint(cs[n]) << 32) | (u64)(0xFFFFFFFFu - (u32)n);
      }
    }
  }
  if (total < 100) {
    int i = tid;  // 256 threads cover flat indices [0,256)
    if (cs[i] == 0.f) {
      int p = atomicAdd(&s_V, 1);
      if (p < 1024) fbuf[p] = (u64)(0xFFFFFFFFu - (u32)i);
    }
  }
  __syncthreads();
  int V = s_V; if (V > 1024) V = 1024;
  const int M = (V <= 128) ? 128 : (V <= 256 ? 256 : (V <= 512 ? 512 : 1024));
  for (int i = V + tid; i < M; i += 256) fbuf[i] = 0ull;
  __syncthreads();

  for (int k = 2; k <= M; k <<= 1) {
    for (int j = k >> 1; j > 0; j >>= 1) {
      for (int i = tid; i < M; i += 256) {
        int l = i ^ j;
        if (l > i) {
          u64 a = fbuf[i], b2 = fbuf[l];
          bool up = ((i & k) == 0);
          if (up ? (a < b2) : (a > b2)) { fbuf[i] = b2; fbuf[l] = a; }
        }
      }
      __syncthreads();
    }
  }

  if (tid < 100) {
    u64 key = fbuf[tid];
    float s = __uint_as_float((u32)(key >> 32));
    int flat = (int)(0xFFFFFFFFu - (u32)key);
    if (flat < 0 || flat >= 8000) { flat = 0; s = 0.f; }
    float mlt = (s > 0.f) ? 1.f : 0.f;
    const float* bx = g_cls_b + ((size_t)b * 8000 + flat) * 4;
    out[(b * 100 + tid) * 4 + 0] = bx[0] * mlt;
    out[(b * 100 + tid) * 4 + 1] = bx[1] * mlt;
    out[(b * 100 + tid) * 4 + 2] = bx[2] * mlt;
    out[(b * 100 + tid) * 4 + 3] = bx[3] * mlt;
    out[6400 + b * 100 + tid] = (float)(flat / 100);
    out[8000 + b * 100 + tid] = s;
  }
}

// ---------------------------------------------------------------------------
extern "C" void kernel_launch(void* const* d_in, const int* in_sizes, int n_in,
                              void* d_out, int out_size) {
  const float* regs = (const float*)d_in[0];
  const float* ctrs = (const float*)d_in[1];
  const float* clfs = (const float*)d_in[2];
  for (int i = 0; i < n_in; i++) {
    if (in_sizes[i] == BBATCH * NN * 4) regs = (const float*)d_in[i];
    else if (in_sizes[i] == BBATCH * NN) ctrs = (const float*)d_in[i];
    else if (in_sizes[i] == BBATCH * NN * NCLS) clfs = (const float*)d_in[i];
  }
  float* out = (float*)d_out;

  dim3 gT(NN / 64, BBATCH);
  k_transpose<<<gT, 256>>>(clfs, ctrs);

  dim3 gS(NCLS, BBATCH);
  k_select<<<gS, 512>>>(regs, clfs, ctrs);

  k_final<<<BBATCH, 256>>>(out);
}